// round 1
// baseline (speedup 1.0000x reference)
#include <cuda_runtime.h>

#define B_   2
#define S_   2048
#define D_   1024
#define H_   16
#define HD_  64
#define MEM_ 512
#define SK_  2560          // MEM_ + S_
#define M_   4096          // B_*S_
#define QT   16            // queries per attention block
#define NTH  256

// Scratch (device globals: no allocation allowed in kernel_launch)
__device__ float g_q[B_*H_*S_*HD_];     // [bh][s][hd]
__device__ float g_k[B_*H_*SK_*HD_];    // [bh][sk][hd] (past at 0..511, new at 512..)
__device__ float g_v[B_*H_*SK_*HD_];
__device__ float g_ctx[B_*S_*D_];       // attention output, (b*s, h*64+hd)

// ---------------------------------------------------------------------------
// GEMM: Y = A(4096x1024) @ W(1024x1024) + bias, with layout-aware epilogue.
// mode 0: write Q head layout; 1: K head layout (+MEM_ row offset);
// mode 2: V head layout; 3: plain row-major to dst (A is ignored, g_ctx used).
// ---------------------------------------------------------------------------
__global__ __launch_bounds__(256) void gemm_kernel(
    const float* __restrict__ A, const float* __restrict__ W,
    const float* __restrict__ bias, float* __restrict__ dst, int mode)
{
    __shared__ float As[16][64];
    __shared__ float Bs[16][64];
    const float* Ap = (mode == 3) ? g_ctx : A;

    int t  = threadIdx.x;
    int tx = t & 15, ty = t >> 4;
    int m0 = blockIdx.y * 64, n0 = blockIdx.x * 64;
    float acc[4][4] = {};

    for (int kt = 0; kt < 1024; kt += 16) {
        #pragma unroll
        for (int i = 0; i < 4; i++) {
            int e  = t + i * 256;
            int ar = e >> 4, ac = e & 15;
            As[ac][ar] = Ap[(m0 + ar) * 1024 + kt + ac];
            int br = e >> 6, bc = e & 63;
            Bs[br][bc] = W[(kt + br) * 1024 + n0 + bc];
        }
        __syncthreads();
        #pragma unroll
        for (int k = 0; k < 16; k++) {
            float a[4], b2[4];
            #pragma unroll
            for (int i = 0; i < 4; i++) a[i]  = As[k][ty * 4 + i];
            #pragma unroll
            for (int j = 0; j < 4; j++) b2[j] = Bs[k][tx * 4 + j];
            #pragma unroll
            for (int i = 0; i < 4; i++)
                #pragma unroll
                for (int j = 0; j < 4; j++)
                    acc[i][j] += a[i] * b2[j];
        }
        __syncthreads();
    }

    #pragma unroll
    for (int i = 0; i < 4; i++) {
        int m = m0 + ty * 4 + i;
        int b = m >> 11, s = m & 2047;
        #pragma unroll
        for (int j = 0; j < 4; j++) {
            int n = n0 + tx * 4 + j;
            float y = acc[i][j] + bias[n];
            int h = n >> 6, hd = n & 63;
            if (mode == 0)
                g_q[((b * H_ + h) * S_ + s) * HD_ + hd] = y;
            else if (mode == 1)
                g_k[((b * H_ + h) * SK_ + MEM_ + s) * HD_ + hd] = y;
            else if (mode == 2)
                g_v[((b * H_ + h) * SK_ + MEM_ + s) * HD_ + hd] = y;
            else
                dst[m * D_ + n] = y;
        }
    }
}

// ---------------------------------------------------------------------------
// Copy past K/V into the head of the concat buffers.
// ---------------------------------------------------------------------------
__global__ void copy_past_kernel(const float* __restrict__ pk,
                                 const float* __restrict__ pv)
{
    int i = blockIdx.x * blockDim.x + threadIdx.x;
    if (i < B_ * H_ * MEM_ * HD_) {
        int bh = i >> 15;          // / (MEM_*HD_)
        int rem = i & 32767;
        g_k[bh * (SK_ * HD_) + rem] = pk[i];
        g_v[bh * (SK_ * HD_) + rem] = pv[i];
    }
}

// Emit new_k/new_v = last MEM_ rows of the concat buffers.
__global__ void copy_new_kernel(float* __restrict__ nk, float* __restrict__ nv)
{
    int i = blockIdx.x * blockDim.x + threadIdx.x;
    if (i < B_ * H_ * MEM_ * HD_) {
        int bh = i >> 15;
        int rem = i & 32767;
        int src = bh * (SK_ * HD_) + S_ * HD_ + rem;  // rows 2048..2559
        nk[i] = g_k[src];
        nv[i] = g_v[src];
    }
}

// ---------------------------------------------------------------------------
// Radix select helpers (exact k-th smallest, 0-indexed) — warp cooperative.
// ---------------------------------------------------------------------------
__device__ __forceinline__ unsigned f2key(float f) {
    unsigned u = __float_as_uint(f);
    return (u & 0x80000000u) ? ~u : (u | 0x80000000u);
}
__device__ __forceinline__ float key2f(unsigned k) {
    unsigned u = (k & 0x80000000u) ? (k ^ 0x80000000u) : ~k;
    return __uint_as_float(u);
}

__device__ float warp_kth(const float* __restrict__ row, int k,
                          unsigned* __restrict__ hist, int lane)
{
    unsigned prefix = 0;
    for (int shift = 24; shift >= 0; shift -= 8) {
        for (int i = lane; i < 256; i += 32) hist[i] = 0;
        __syncwarp();
        unsigned hi_mask = (shift == 24) ? 0u : (0xFFFFFFFFu << (shift + 8));
        for (int i = lane; i < SK_; i += 32) {
            unsigned key = f2key(row[i]);
            if ((key & hi_mask) == prefix)
                atomicAdd(&hist[(key >> shift) & 255], 1u);
        }
        __syncwarp();
        unsigned cnt[8], local = 0;
        #pragma unroll
        for (int j = 0; j < 8; j++) { cnt[j] = hist[lane * 8 + j]; local += cnt[j]; }
        unsigned x = local;
        #pragma unroll
        for (int off = 1; off < 32; off <<= 1) {
            unsigned y = __shfl_up_sync(0xffffffffu, x, off);
            if (lane >= off) x += y;
        }
        unsigned incl = x, excl = x - local;
        bool flag = ((unsigned)k >= excl) && ((unsigned)k < incl);
        unsigned bal = __ballot_sync(0xffffffffu, flag);
        int src = __ffs(bal) - 1;
        int digit = 0, newk = 0;
        if (lane == src) {
            unsigned c = excl;
            int j = 0;
            for (; j < 8; j++) { if (c + cnt[j] > (unsigned)k) break; c += cnt[j]; }
            digit = lane * 8 + j;
            newk  = k - (int)c;
        }
        digit = __shfl_sync(0xffffffffu, digit, src);
        k     = __shfl_sync(0xffffffffu, newk,  src);
        prefix |= ((unsigned)digit) << shift;
        __syncwarp();
    }
    return key2f(prefix);
}

// ---------------------------------------------------------------------------
// Attention: one block = (bh, 16-query tile). Scores for all 2560 keys kept
// in SMEM; exact rank-256 threshold (== quantile keep-set); masked softmax;
// attn @ V. Writes ctx in (b*s, h*64+hd) layout for the output projection.
// Dynamic smem: scores 16*2560 f32 + stage 16*68 f32 + hist 8*256 u32.
// ---------------------------------------------------------------------------
#define STAGE_LD 68
#define ATT_SMEM ((QT * SK_ + 16 * STAGE_LD + 8 * 256) * 4)

__global__ __launch_bounds__(NTH, 1) void attn_kernel(const int* __restrict__ amask)
{
    extern __shared__ float dyn[];
    float*    scores = dyn;                               // QT * SK_
    float*    stage  = dyn + QT * SK_;                    // 16 * STAGE_LD
    unsigned* hist   = (unsigned*)(dyn + QT * SK_ + 16 * STAGE_LD); // 8*256
    __shared__ float s_inv[QT];

    int bh = blockIdx.y;
    int b  = bh >> 4;
    int h  = bh & 15;
    int q0 = blockIdx.x * QT;
    int t  = threadIdx.x;
    int qi = t >> 4;
    int kk = t & 15;
    int w  = t >> 5, lane = t & 31;

    // Load this thread's query row into registers (float4 x16)
    const float4* qrow = (const float4*)(g_q + ((size_t)bh * S_ + q0 + qi) * HD_);
    float4 qv[16];
    #pragma unroll
    for (int u = 0; u < 16; u++) qv[u] = qrow[u];

    const float* K = g_k + (size_t)bh * SK_ * HD_;
    const float* V = g_v + (size_t)bh * SK_ * HD_;

    // ---- Phase 1: scores = (Q K^T) * scale -------------------------------
    for (int kb = 0; kb < SK_; kb += 16) {
        for (int e = t; e < 16 * 64; e += NTH) {
            int r = e >> 6, c = e & 63;
            stage[r * STAGE_LD + c] = K[(kb + r) * 64 + c];
        }
        __syncthreads();
        const float4* krow = (const float4*)(stage + kk * STAGE_LD);
        float s = 0.f;
        #pragma unroll
        for (int u = 0; u < 16; u++) {
            float4 kv = krow[u];
            s += qv[u].x * kv.x + qv[u].y * kv.y + qv[u].z * kv.z + qv[u].w * kv.w;
        }
        scores[qi * SK_ + kb + kk] = s * 0.125f;  // 1/sqrt(64)
        __syncthreads();
    }

    // ---- Phase 2: exact rank-256 threshold + masked softmax (per warp) ---
    const int* am = amask + b * S_;
    for (int r = w; r < QT; r += 8) {
        float* row = scores + r * SK_;
        float v = warp_kth(row, 256, hist + w * 256, lane);  // keep iff x >= v
        float m = -1e30f;
        for (int i = lane; i < SK_; i += 32) {
            float x = row[i];
            bool keep = (x >= v) && (i < MEM_ || am[i - MEM_] != 0);
            if (keep) m = fmaxf(m, x);
        }
        #pragma unroll
        for (int off = 16; off; off >>= 1)
            m = fmaxf(m, __shfl_xor_sync(0xffffffffu, m, off));
        float den = 0.f;
        for (int i = lane; i < SK_; i += 32) {
            float x = row[i];
            bool keep = (x >= v) && (i < MEM_ || am[i - MEM_] != 0);
            float p = keep ? __expf(x - m) : 0.f;
            row[i] = p;
            den += p;
        }
        #pragma unroll
        for (int off = 16; off; off >>= 1)
            den += __shfl_xor_sync(0xffffffffu, den, off);
        if (lane == 0) s_inv[r] = 1.0f / den;
    }
    __syncthreads();

    // ---- Phase 3: attn @ V ----------------------------------------------
    int dg = t & 15;                      // dim group: dims [4dg, 4dg+4)
    float4 acc = make_float4(0.f, 0.f, 0.f, 0.f);
    for (int kb = 0; kb < SK_; kb += 16) {
        for (int e = t; e < 16 * 64; e += NTH) {
            int r = e >> 6, c = e & 63;
            stage[r * STAGE_LD + c] = V[(kb + r) * 64 + c];
        }
        __syncthreads();
        #pragma unroll
        for (int k2 = 0; k2 < 16; k2++) {
            float p = scores[qi * SK_ + kb + k2];
            float4 vv = *(const float4*)(stage + k2 * STAGE_LD + dg * 4);
            acc.x += p * vv.x; acc.y += p * vv.y;
            acc.z += p * vv.z; acc.w += p * vv.w;
        }
        __syncthreads();
    }
    float inv = s_inv[qi];
    float* orow = g_ctx + ((size_t)(b * S_ + q0 + qi) * D_) + h * HD_ + dg * 4;
    orow[0] = acc.x * inv;
    orow[1] = acc.y * inv;
    orow[2] = acc.z * inv;
    orow[3] = acc.w * inv;
}

// ---------------------------------------------------------------------------
extern "C" void kernel_launch(void* const* d_in, const int* in_sizes, int n_in,
                              void* d_out, int out_size)
{
    const float* hs     = (const float*)d_in[0];
    const int*   amask  = (const int*)  d_in[1];
    const float* past_k = (const float*)d_in[2];
    const float* past_v = (const float*)d_in[3];
    const float* Wq = (const float*)d_in[4];
    const float* bq = (const float*)d_in[5];
    const float* Wk = (const float*)d_in[6];
    const float* bk = (const float*)d_in[7];
    const float* Wv = (const float*)d_in[8];
    const float* bv = (const float*)d_in[9];
    const float* Wo = (const float*)d_in[10];
    const float* bo = (const float*)d_in[11];
    float* out = (float*)d_out;

    cudaFuncSetAttribute(attn_kernel,
                         cudaFuncAttributeMaxDynamicSharedMemorySize, ATT_SMEM);

    // 1) KV cache concat (past)
    copy_past_kernel<<<4096, 256>>>(past_k, past_v);

    // 2) QKV projections (head-split epilogues)
    dim3 ggrid(16, 64);
    gemm_kernel<<<ggrid, 256>>>(hs, Wq, bq, nullptr, 0);
    gemm_kernel<<<ggrid, 256>>>(hs, Wk, bk, nullptr, 1);
    gemm_kernel<<<ggrid, 256>>>(hs, Wv, bv, nullptr, 2);

    // 3) sparse-threshold attention
    dim3 agrid(S_ / QT, B_ * H_);
    attn_kernel<<<agrid, NTH, ATT_SMEM>>>(amask);

    // 4) output projection -> out
    gemm_kernel<<<ggrid, 256>>>(nullptr, Wo, bo, out, 3);

    // 5) new_k / new_v (last MEM_ rows of concat caches)
    float* nk = out + (size_t)B_ * S_ * D_;              // 4194304
    float* nv = nk + (size_t)B_ * H_ * MEM_ * HD_;       // +1048576
    copy_new_kernel<<<4096, 256>>>(nk, nv);
}

// round 2
// speedup vs baseline: 2.7757x; 2.7757x over previous
#include <cuda_runtime.h>

#define B_   2
#define S_   2048
#define D_   1024
#define H_   16
#define HD_  64
#define MEM_ 512
#define SK_  2560          // MEM_ + S_
#define QT   16            // queries per attention block
#define NTH  256

#define RS_      2562                  // scores row stride (bank-conflict-free P loads)
#define SCORES_F (QT * RS_)            // 40992 floats
#define REGA_F   8704                  // union: KT 16x516=8256 | Vs 128x68=8704 | hist 2048 u32
#define QS_F     (64 * 20)             // 1280 floats
#define OUT_F    (QT * HD_)            // 1024 floats
#define ATT_SMEM ((SCORES_F + REGA_F + QS_F + OUT_F) * 4)   // 208,000 B

// Scratch (device globals: no allocation allowed in kernel_launch)
__device__ float g_q[B_*H_*S_*HD_];     // [bh][s][hd]
__device__ float g_k[B_*H_*SK_*HD_];    // [bh][sk][hd] (past at 0..511, new at 512..)
__device__ float g_v[B_*H_*SK_*HD_];
__device__ float g_ctx[B_*S_*D_];       // attention output, (b*s, h*64+hd)

// ---------------------------------------------------------------------------
// GEMM: Y = A(4096x1024) @ W(1024x1024) + bias, with layout-aware epilogue.
// mode 0: Q head layout; 1: K head layout (+MEM_ rows); 2: V; 3: row-major out.
// ---------------------------------------------------------------------------
__global__ __launch_bounds__(256) void gemm_kernel(
    const float* __restrict__ A, const float* __restrict__ W,
    const float* __restrict__ bias, float* __restrict__ dst, int mode)
{
    __shared__ float As[16][64];
    __shared__ float Bs[16][64];
    const float* Ap = (mode == 3) ? g_ctx : A;

    int t  = threadIdx.x;
    int tx = t & 15, ty = t >> 4;
    int m0 = blockIdx.y * 64, n0 = blockIdx.x * 64;
    float acc[4][4] = {};

    for (int kt = 0; kt < 1024; kt += 16) {
        #pragma unroll
        for (int i = 0; i < 4; i++) {
            int e  = t + i * 256;
            int ar = e >> 4, ac = e & 15;
            As[ac][ar] = Ap[(m0 + ar) * 1024 + kt + ac];
            int br = e >> 6, bc = e & 63;
            Bs[br][bc] = W[(kt + br) * 1024 + n0 + bc];
        }
        __syncthreads();
        #pragma unroll
        for (int k = 0; k < 16; k++) {
            float a[4], b2[4];
            #pragma unroll
            for (int i = 0; i < 4; i++) a[i]  = As[k][ty * 4 + i];
            #pragma unroll
            for (int j = 0; j < 4; j++) b2[j] = Bs[k][tx * 4 + j];
            #pragma unroll
            for (int i = 0; i < 4; i++)
                #pragma unroll
                for (int j = 0; j < 4; j++)
                    acc[i][j] += a[i] * b2[j];
        }
        __syncthreads();
    }

    #pragma unroll
    for (int i = 0; i < 4; i++) {
        int m = m0 + ty * 4 + i;
        int b = m >> 11, s = m & 2047;
        #pragma unroll
        for (int j = 0; j < 4; j++) {
            int n = n0 + tx * 4 + j;
            float y = acc[i][j] + bias[n];
            int h = n >> 6, hd = n & 63;
            if (mode == 0)
                g_q[((b * H_ + h) * S_ + s) * HD_ + hd] = y;
            else if (mode == 1)
                g_k[((b * H_ + h) * SK_ + MEM_ + s) * HD_ + hd] = y;
            else if (mode == 2)
                g_v[((b * H_ + h) * SK_ + MEM_ + s) * HD_ + hd] = y;
            else
                dst[m * D_ + n] = y;
        }
    }
}

__global__ void copy_past_kernel(const float* __restrict__ pk,
                                 const float* __restrict__ pv)
{
    int i = blockIdx.x * blockDim.x + threadIdx.x;
    if (i < B_ * H_ * MEM_ * HD_) {
        int bh = i >> 15;
        int rem = i & 32767;
        g_k[bh * (SK_ * HD_) + rem] = pk[i];
        g_v[bh * (SK_ * HD_) + rem] = pv[i];
    }
}

__global__ void copy_new_kernel(float* __restrict__ nk, float* __restrict__ nv)
{
    int i = blockIdx.x * blockDim.x + threadIdx.x;
    if (i < B_ * H_ * MEM_ * HD_) {
        int bh = i >> 15;
        int rem = i & 32767;
        int src = bh * (SK_ * HD_) + S_ * HD_ + rem;
        nk[i] = g_k[src];
        nv[i] = g_v[src];
    }
}

// ---------------------------------------------------------------------------
// Radix select (exact k-th smallest, 0-indexed) — warp cooperative.
// ---------------------------------------------------------------------------
__device__ __forceinline__ unsigned f2key(float f) {
    unsigned u = __float_as_uint(f);
    return (u & 0x80000000u) ? ~u : (u | 0x80000000u);
}
__device__ __forceinline__ float key2f(unsigned k) {
    unsigned u = (k & 0x80000000u) ? (k ^ 0x80000000u) : ~k;
    return __uint_as_float(u);
}

__device__ float warp_kth(const float* __restrict__ row, int k,
                          unsigned* __restrict__ hist, int lane)
{
    unsigned prefix = 0;
    for (int shift = 24; shift >= 0; shift -= 8) {
        for (int i = lane; i < 256; i += 32) hist[i] = 0;
        __syncwarp();
        unsigned hi_mask = (shift == 24) ? 0u : (0xFFFFFFFFu << (shift + 8));
        for (int i = lane; i < SK_; i += 32) {
            unsigned key = f2key(row[i]);
            if ((key & hi_mask) == prefix)
                atomicAdd(&hist[(key >> shift) & 255], 1u);
        }
        __syncwarp();
        unsigned cnt[8], local = 0;
        #pragma unroll
        for (int j = 0; j < 8; j++) { cnt[j] = hist[lane * 8 + j]; local += cnt[j]; }
        unsigned x = local;
        #pragma unroll
        for (int off = 1; off < 32; off <<= 1) {
            unsigned y = __shfl_up_sync(0xffffffffu, x, off);
            if (lane >= off) x += y;
        }
        unsigned incl = x, excl = x - local;
        bool flag = ((unsigned)k >= excl) && ((unsigned)k < incl);
        unsigned bal = __ballot_sync(0xffffffffu, flag);
        int src = __ffs(bal) - 1;
        int digit = 0, newk = 0;
        if (lane == src) {
            unsigned c = excl;
            int j = 0;
            for (; j < 8; j++) { if (c + cnt[j] > (unsigned)k) break; c += cnt[j]; }
            digit = lane * 8 + j;
            newk  = k - (int)c;
        }
        digit = __shfl_sync(0xffffffffu, digit, src);
        k     = __shfl_sync(0xffffffffu, newk,  src);
        prefix |= ((unsigned)digit) << shift;
        __syncwarp();
    }
    return key2f(prefix);
}

// ---------------------------------------------------------------------------
// Attention: one block = (bh, 16-query tile). Register-tiled GEMM phases.
//  P1: scores = Q K^T * scale.  4q x 8k per thread vs transposed K stage.
//  P2: exact rank-256 threshold (= quantile keep-set), masked softmax in place.
//  P3: ctx = P V.  4q x 8d per thread, 8-way split-K, smem-atomic reduction.
// ---------------------------------------------------------------------------
__global__ __launch_bounds__(NTH, 1) void attn_kernel(const int* __restrict__ amask)
{
    extern __shared__ float dyn[];
    float*    scores = dyn;                         // [16][RS_]
    float*    regA   = dyn + SCORES_F;              // KT | Vs | hist union
    unsigned* hist   = (unsigned*)regA;
    float*    Qs     = dyn + SCORES_F + REGA_F;     // [64][20]
    float*    out_s  = Qs + QS_F;                   // [16][64]
    __shared__ float s_inv[QT];

    int bh = blockIdx.y;
    int b  = bh >> 4;
    int h  = bh & 15;
    int q0blk = blockIdx.x * QT;
    int t  = threadIdx.x;
    int w  = t >> 5, lane = t & 31;

    const float* Qg = g_q + ((size_t)bh * S_ + q0blk) * HD_;
    const float* K  = g_k + (size_t)bh * SK_ * HD_;
    const float* V  = g_v + (size_t)bh * SK_ * HD_;

    // Stage Q^T: Qs[d][q], stride 20
    {
        int q = t >> 4, jj = t & 15;
        float4 v = *(const float4*)(Qg + q * HD_ + jj * 4);
        Qs[(jj * 4 + 0) * 20 + q] = v.x;
        Qs[(jj * 4 + 1) * 20 + q] = v.y;
        Qs[(jj * 4 + 2) * 20 + q] = v.z;
        Qs[(jj * 4 + 3) * 20 + q] = v.w;
    }

    // ---- Phase 1: scores = Q K^T * scale ---------------------------------
    {
        int qg = t >> 6;          // 0..3  (constant within warp -> a broadcast)
        int kg = t & 63;          // 0..63
        for (int tile = 0; tile < 5; tile++) {
            float acc[4][8] = {};
            for (int dc = 0; dc < 4; dc++) {
                __syncthreads();
                // stage KT[16][516]: dims dc*16.., keys tile*512..
                #pragma unroll
                for (int it = 0; it < 8; it++) {
                    int e = t + it * NTH;            // 0..2047
                    int key = e >> 2, jj = e & 3;
                    float4 v = *(const float4*)(K + (size_t)(tile * 512 + key) * HD_
                                                  + dc * 16 + jj * 4);
                    regA[(jj * 4 + 0) * 516 + key] = v.x;
                    regA[(jj * 4 + 1) * 516 + key] = v.y;
                    regA[(jj * 4 + 2) * 516 + key] = v.z;
                    regA[(jj * 4 + 3) * 516 + key] = v.w;
                }
                __syncthreads();
                #pragma unroll
                for (int k = 0; k < 16; k++) {
                    float4 a  = *(const float4*)(Qs + (dc * 16 + k) * 20 + qg * 4);
                    float4 b0 = *(const float4*)(regA + k * 516 + kg * 4);
                    float4 b1 = *(const float4*)(regA + k * 516 + 256 + kg * 4);
                    float av[4] = {a.x, a.y, a.z, a.w};
                    float bv[8] = {b0.x, b0.y, b0.z, b0.w, b1.x, b1.y, b1.z, b1.w};
                    #pragma unroll
                    for (int i = 0; i < 4; i++)
                        #pragma unroll
                        for (int j = 0; j < 8; j++)
                            acc[i][j] += av[i] * bv[j];
                }
            }
            #pragma unroll
            for (int i = 0; i < 4; i++) {
                float* row = scores + (qg * 4 + i) * RS_ + tile * 512;
                #pragma unroll
                for (int j = 0; j < 4; j++)
                    row[kg * 4 + j] = acc[i][j] * 0.125f;
                #pragma unroll
                for (int j = 0; j < 4; j++)
                    row[256 + kg * 4 + j] = acc[i][4 + j] * 0.125f;
            }
        }
    }
    __syncthreads();

    // ---- Phase 2: rank-256 threshold + masked softmax (per warp, 2 rows) -
    const int* am = amask + b * S_;
    for (int r = w; r < QT; r += 8) {
        float* row = scores + r * RS_;
        float v = warp_kth(row, 256, hist + w * 256, lane);  // keep iff x >= v
        float m = -1e30f;
        for (int i = lane; i < SK_; i += 32) {
            float x = row[i];
            bool keep = (x >= v) && (i < MEM_ || am[i - MEM_] != 0);
            if (keep) m = fmaxf(m, x);
        }
        #pragma unroll
        for (int off = 16; off; off >>= 1)
            m = fmaxf(m, __shfl_xor_sync(0xffffffffu, m, off));
        float den = 0.f;
        for (int i = lane; i < SK_; i += 32) {
            float x = row[i];
            bool keep = (x >= v) && (i < MEM_ || am[i - MEM_] != 0);
            float p = keep ? __expf(x - m) : 0.f;
            row[i] = p;
            den += p;
        }
        #pragma unroll
        for (int off = 16; off; off >>= 1)
            den += __shfl_xor_sync(0xffffffffu, den, off);
        if (lane == 0) s_inv[r] = 1.0f / den;
    }
    __syncthreads();

    // zero out_s
    {
        float4 z = make_float4(0.f, 0.f, 0.f, 0.f);
        *(float4*)(out_s + t * 4) = z;
    }

    // ---- Phase 3: ctx = P @ V -------------------------------------------
    {
        int kp = t >> 5;               // 0..7  split-K partition (= warp)
        int qg = lane >> 3;            // 0..3
        int dg = lane & 7;             // 0..7
        int q0 = qg * 4, d0 = dg * 8;
        float acc[4][8] = {};
        for (int chunk = 0; chunk < 20; chunk++) {
            __syncthreads();
            // stage Vs[128][68]
            #pragma unroll
            for (int it = 0; it < 8; it++) {
                int e = t + it * NTH;          // 0..2047
                int key = e >> 4, jj = e & 15;
                float4 v = *(const float4*)(V + (size_t)(chunk * 128 + key) * HD_ + jj * 4);
                *(float4*)(regA + key * 68 + jj * 4) = v;
            }
            __syncthreads();
            #pragma unroll
            for (int kk = 0; kk < 16; kk++) {
                int kl = kp * 16 + kk;
                int kg2 = chunk * 128 + kl;
                float av[4];
                #pragma unroll
                for (int i = 0; i < 4; i++)
                    av[i] = scores[(q0 + i) * RS_ + kg2];
                float4 b0 = *(const float4*)(regA + kl * 68 + d0);
                float4 b1 = *(const float4*)(regA + kl * 68 + d0 + 4);
                float bv[8] = {b0.x, b0.y, b0.z, b0.w, b1.x, b1.y, b1.z, b1.w};
                #pragma unroll
                for (int i = 0; i < 4; i++)
                    #pragma unroll
                    for (int j = 0; j < 8; j++)
                        acc[i][j] += av[i] * bv[j];
            }
        }
        // split-K reduction into out_s
        #pragma unroll
        for (int i = 0; i < 4; i++)
            #pragma unroll
            for (int j = 0; j < 8; j++)
                atomicAdd(&out_s[(q0 + i) * HD_ + d0 + j], acc[i][j]);
    }
    __syncthreads();

    // final write with 1/den scaling
    {
        int idx = t * 4;
        int q = idx >> 6, d = idx & 63;
        float inv = s_inv[q];
        float4 v = *(const float4*)(out_s + idx);
        float* orow = g_ctx + ((size_t)(b * S_ + q0blk + q) * D_) + h * HD_ + d;
        orow[0] = v.x * inv;
        orow[1] = v.y * inv;
        orow[2] = v.z * inv;
        orow[3] = v.w * inv;
    }
}

// ---------------------------------------------------------------------------
extern "C" void kernel_launch(void* const* d_in, const int* in_sizes, int n_in,
                              void* d_out, int out_size)
{
    const float* hs     = (const float*)d_in[0];
    const int*   amask  = (const int*)  d_in[1];
    const float* past_k = (const float*)d_in[2];
    const float* past_v = (const float*)d_in[3];
    const float* Wq = (const float*)d_in[4];
    const float* bq = (const float*)d_in[5];
    const float* Wk = (const float*)d_in[6];
    const float* bk = (const float*)d_in[7];
    const float* Wv = (const float*)d_in[8];
    const float* bv = (const float*)d_in[9];
    const float* Wo = (const float*)d_in[10];
    const float* bo = (const float*)d_in[11];
    float* out = (float*)d_out;

    cudaFuncSetAttribute(attn_kernel,
                         cudaFuncAttributeMaxDynamicSharedMemorySize, ATT_SMEM);

    copy_past_kernel<<<4096, 256>>>(past_k, past_v);

    dim3 ggrid(16, 64);
    gemm_kernel<<<ggrid, 256>>>(hs, Wq, bq, nullptr, 0);
    gemm_kernel<<<ggrid, 256>>>(hs, Wk, bk, nullptr, 1);
    gemm_kernel<<<ggrid, 256>>>(hs, Wv, bv, nullptr, 2);

    dim3 agrid(S_ / QT, B_ * H_);
    attn_kernel<<<agrid, NTH, ATT_SMEM>>>(amask);

    gemm_kernel<<<ggrid, 256>>>(nullptr, Wo, bo, out, 3);

    float* nk = out + (size_t)B_ * S_ * D_;
    float* nv = nk + (size_t)B_ * H_ * MEM_ * HD_;
    copy_new_kernel<<<4096, 256>>>(nk, nv);
}

// round 4
// speedup vs baseline: 5.1604x; 1.8591x over previous
#include <cuda_runtime.h>

#define B_   2
#define S_   2048
#define D_   1024
#define H_   16
#define HD_  64
#define MEM_ 512
#define SK_  2560
#define BH_  32
#define NROW (BH_*S_)   // 65536

// Scratch (static device allocs only)
__device__ float  g_q[BH_*S_*HD_];
__device__ float  g_k[BH_*SK_*HD_];
__device__ float  g_v[BH_*SK_*HD_];
__device__ float  g_ctx[B_*S_*D_];
__device__ float  g_scores[(size_t)NROW*SK_];   // 671 MB
__device__ float4 g_stats[NROW];                // thr, max, 1/den

__device__ __forceinline__ unsigned f2tf(float f){
    unsigned r; asm("cvt.rna.tf32.f32 %0, %1;" : "=r"(r) : "f"(f)); return r;
}
// 3xTF32 split: x = hi + lo (residual exact in f32)
__device__ __forceinline__ void tfsplit(float x, unsigned& h, unsigned& l){
    h = f2tf(x);
    l = f2tf(x - __uint_as_float(h));
}
__device__ __forceinline__ void mma8(float* c, const unsigned* a, const unsigned* b){
    asm volatile("mma.sync.aligned.m16n8k8.row.col.f32.tf32.tf32.f32 "
      "{%0,%1,%2,%3}, {%4,%5,%6,%7}, {%8,%9}, {%0,%1,%2,%3};\n"
      : "+f"(c[0]), "+f"(c[1]), "+f"(c[2]), "+f"(c[3])
      : "r"(a[0]),"r"(a[1]),"r"(a[2]),"r"(a[3]), "r"(b[0]),"r"(b[1]));
}
// C += A*B with 3xTF32 compensation
__device__ __forceinline__ void mma8x3(float* c, const unsigned* ah, const unsigned* al,
                                       const unsigned* bh, const unsigned* bl){
    mma8(c, al, bh);
    mma8(c, ah, bl);
    mma8(c, ah, bh);
}

// ---------------------------------------------------------------------------
// Dense GEMM (3xTF32): C(4096x1024) = A(4096x1024)@W(1024x1024)+bias.
// Block 128x128, BK=16 double-buffered, 8 warps (2m x 4n), warp tile 64x32.
// mode 0/1/2: head-split epilogue into g_q/g_k/g_v; mode 3: row-major dst.
// ---------------------------------------------------------------------------
__global__ __launch_bounds__(256) void gemm4k(
    const float* __restrict__ A, const float* __restrict__ W,
    const float* __restrict__ bias, float* __restrict__ dst, int mode)
{
    __shared__ float As[2][128*20];   // [m][k] f32, stride 20
    __shared__ float Bs[2][16*136];   // [k][n] f32, stride 136
    const float* Ap = (mode==3) ? g_ctx : A;
    const int t = threadIdx.x;
    const int m0 = blockIdx.y*128, n0 = blockIdx.x*128;
    const int w = t>>5, lane = t&31, g = lane>>2, tig = lane&3;
    const int wm = w>>2, wn = w&3;

    const int am_r = t>>2;          // 0..63
    const int am_k = (t&3)*4;
    const int bm_k = t>>5;          // 0..7
    const int bm_n = (t&31)*4;

    const float* Arow0 = Ap + (size_t)(m0+am_r)*1024 + am_k;
    const float* Arow1 = Arow0 + (size_t)64*1024;
    const float* Wrow0 = W + (size_t)bm_k*1024 + n0 + bm_n;
    const float* Wrow1 = Wrow0 + (size_t)8*1024;

    float acc[4][4][4];
    #pragma unroll
    for(int i=0;i<4;i++)
        #pragma unroll
        for(int j=0;j<4;j++)
            #pragma unroll
            for(int c=0;c<4;c++) acc[i][j][c]=0.f;

    float4 la0,la1,lb0,lb1;
    auto ldg = [&](int kt){
        la0 = *(const float4*)(Arow0 + kt*16);
        la1 = *(const float4*)(Arow1 + kt*16);
        lb0 = *(const float4*)(Wrow0 + (size_t)kt*16*1024);
        lb1 = *(const float4*)(Wrow1 + (size_t)kt*16*1024);
    };
    auto sts = [&](int buf){
        *(float4*)&As[buf][am_r*20 + am_k]      = la0;
        *(float4*)&As[buf][(am_r+64)*20 + am_k] = la1;
        *(float4*)&Bs[buf][bm_k*136 + bm_n]     = lb0;
        *(float4*)&Bs[buf][(bm_k+8)*136 + bm_n] = lb1;
    };
    auto compute = [&](int buf){
        #pragma unroll
        for(int kk=0;kk<2;kk++){
            unsigned ah[4][4], al[4][4], bh[4][2], bl[4][2];
            #pragma unroll
            for(int mi=0;mi<4;mi++){
                const float* p = &As[buf][(wm*64+mi*16+g)*20 + kk*8 + tig];
                tfsplit(p[0],      ah[mi][0], al[mi][0]);
                tfsplit(p[8*20],   ah[mi][1], al[mi][1]);
                tfsplit(p[4],      ah[mi][2], al[mi][2]);
                tfsplit(p[8*20+4], ah[mi][3], al[mi][3]);
            }
            #pragma unroll
            for(int nj=0;nj<4;nj++){
                const float* p = &Bs[buf][(kk*8+tig)*136 + wn*32+nj*8+g];
                tfsplit(p[0],     bh[nj][0], bl[nj][0]);
                tfsplit(p[4*136], bh[nj][1], bl[nj][1]);
            }
            #pragma unroll
            for(int mi=0;mi<4;mi++)
                #pragma unroll
                for(int nj=0;nj<4;nj++)
                    mma8x3(acc[mi][nj], ah[mi], al[mi], bh[nj], bl[nj]);
        }
    };

    ldg(0); sts(0); __syncthreads();
    for(int kt=0;kt<64;kt++){
        if(kt<63) ldg(kt+1);
        compute(kt&1);
        if(kt<63){ sts((kt+1)&1); __syncthreads(); }
    }

    // epilogue
    const int b = m0>>11;
    #pragma unroll
    for(int nj=0;nj<4;nj++){
        int c0 = n0 + wn*32 + nj*8 + 2*tig;
        float bv0 = bias[c0], bv1 = bias[c0+1];
        int h = c0>>6, hd = c0&63;
        #pragma unroll
        for(int mi=0;mi<4;mi++){
            int r0 = m0 + wm*64 + mi*16 + g;
            int s0 = r0 & 2047;
            float2 v0 = {acc[mi][nj][0]+bv0, acc[mi][nj][1]+bv1};
            float2 v1 = {acc[mi][nj][2]+bv0, acc[mi][nj][3]+bv1};
            if(mode==3){
                *(float2*)(dst + (size_t)r0*1024 + c0)     = v0;
                *(float2*)(dst + (size_t)(r0+8)*1024 + c0) = v1;
            } else {
                float* base = (mode==0)? g_q : (mode==1? g_k : g_v);
                size_t roff = (mode==0)? ((size_t)(b*16+h)*S_)
                                        : ((size_t)(b*16+h)*SK_ + MEM_);
                *(float2*)(base + (roff + s0)*64 + hd)     = v0;
                *(float2*)(base + (roff + s0 + 8)*64 + hd) = v1;
            }
        }
    }
}

__global__ void copy_past_kernel(const float* __restrict__ pk,
                                 const float* __restrict__ pv)
{
    int i = blockIdx.x * blockDim.x + threadIdx.x;
    if (i < BH_ * MEM_ * HD_) {
        int bh = i >> 15, rem = i & 32767;
        g_k[(size_t)bh * (SK_ * HD_) + rem] = pk[i];
        g_v[(size_t)bh * (SK_ * HD_) + rem] = pv[i];
    }
}
__global__ void copy_new_kernel(float* __restrict__ nk, float* __restrict__ nv)
{
    int i = blockIdx.x * blockDim.x + threadIdx.x;
    if (i < BH_ * MEM_ * HD_) {
        int bh = i >> 15, rem = i & 32767;
        size_t src = (size_t)bh * (SK_ * HD_) + S_ * HD_ + rem;
        nk[i] = g_k[src];
        nv[i] = g_v[src];
    }
}

// ---------------------------------------------------------------------------
// scores = (Q K^T) * 0.125 -> g_scores. 3xTF32, K=64. Block 128x128 per bh.
// ---------------------------------------------------------------------------
__global__ __launch_bounds__(256) void scores_k()
{
    extern __shared__ float sh[];
    float* Qs = sh;               // [128][68]
    float* Ks = sh + 128*68;      // [128][68]  (K is [n][k] already)
    const int z = blockIdx.z;
    const int m0 = blockIdx.y*128, n0 = blockIdx.x*128;
    const int t = threadIdx.x, w = t>>5, lane=t&31, g=lane>>2, tig=lane&3;
    const int wm = w>>2, wn = w&3;
    const float* Q = g_q + ((size_t)z*S_ + m0)*64;
    const float* K = g_k + ((size_t)z*SK_ + n0)*64;

    #pragma unroll
    for(int i=0;i<8;i++){
        int idx = t + i*256, r = idx>>4, c = (idx&15)*4;
        *(float4*)&Qs[r*68+c] = *(const float4*)(Q + (size_t)r*64 + c);
        *(float4*)&Ks[r*68+c] = *(const float4*)(K + (size_t)r*64 + c);
    }
    __syncthreads();

    float acc[4][4][4] = {};
    #pragma unroll
    for(int kk=0;kk<8;kk++){
        unsigned ah[4][4], al[4][4], bh[4][2], bl[4][2];
        #pragma unroll
        for(int mi=0;mi<4;mi++){
            const float* p = &Qs[(wm*64+mi*16+g)*68 + kk*8 + tig];
            tfsplit(p[0],      ah[mi][0], al[mi][0]);
            tfsplit(p[8*68],   ah[mi][1], al[mi][1]);
            tfsplit(p[4],      ah[mi][2], al[mi][2]);
            tfsplit(p[8*68+4], ah[mi][3], al[mi][3]);
        }
        #pragma unroll
        for(int nj=0;nj<4;nj++){
            const float* p = &Ks[(wn*32+nj*8+g)*68 + kk*8 + tig];
            tfsplit(p[0], bh[nj][0], bl[nj][0]);
            tfsplit(p[4], bh[nj][1], bl[nj][1]);
        }
        #pragma unroll
        for(int mi=0;mi<4;mi++)
            #pragma unroll
            for(int nj=0;nj<4;nj++)
                mma8x3(acc[mi][nj], ah[mi], al[mi], bh[nj], bl[nj]);
    }

    float* out = g_scores + ((size_t)(z*S_ + m0))*SK_ + n0;
    #pragma unroll
    for(int mi=0;mi<4;mi++){
        int r0 = wm*64+mi*16+g;
        #pragma unroll
        for(int nj=0;nj<4;nj++){
            int c0 = wn*32+nj*8+2*tig;
            float2 v0 = {acc[mi][nj][0]*0.125f, acc[mi][nj][1]*0.125f};
            float2 v1 = {acc[mi][nj][2]*0.125f, acc[mi][nj][3]*0.125f};
            *(float2*)(out + (size_t)r0*SK_ + c0)     = v0;
            *(float2*)(out + (size_t)(r0+8)*SK_ + c0) = v1;
        }
    }
}

// ---------------------------------------------------------------------------
// Radix select (exact k-th smallest) — warp cooperative on smem row.
// ---------------------------------------------------------------------------
__device__ __forceinline__ unsigned f2key(float f) {
    unsigned u = __float_as_uint(f);
    return (u & 0x80000000u) ? ~u : (u | 0x80000000u);
}
__device__ __forceinline__ float key2f(unsigned k) {
    unsigned u = (k & 0x80000000u) ? (k ^ 0x80000000u) : ~k;
    return __uint_as_float(u);
}
__device__ float warp_kth(const float* __restrict__ row, int k,
                          unsigned* __restrict__ hist, int lane)
{
    unsigned prefix = 0;
    for (int shift = 24; shift >= 0; shift -= 8) {
        for (int i = lane; i < 256; i += 32) hist[i] = 0;
        __syncwarp();
        unsigned hi_mask = (shift == 24) ? 0u : (0xFFFFFFFFu << (shift + 8));
        for (int i = lane; i < SK_; i += 32) {
            unsigned key = f2key(row[i]);
            if ((key & hi_mask) == prefix)
                atomicAdd(&hist[(key >> shift) & 255], 1u);
        }
        __syncwarp();
        unsigned cnt[8], local = 0;
        #pragma unroll
        for (int j = 0; j < 8; j++) { cnt[j] = hist[lane*8+j]; local += cnt[j]; }
        unsigned x = local;
        #pragma unroll
        for (int off = 1; off < 32; off <<= 1) {
            unsigned y = __shfl_up_sync(0xffffffffu, x, off);
            if (lane >= off) x += y;
        }
        unsigned incl = x, excl = x - local;
        bool flag = ((unsigned)k >= excl) && ((unsigned)k < incl);
        unsigned bal = __ballot_sync(0xffffffffu, flag);
        int src = __ffs(bal) - 1;
        int digit = 0, newk = 0;
        if (lane == src) {
            unsigned c = excl; int j = 0;
            for (; j < 8; j++) { if (c + cnt[j] > (unsigned)k) break; c += cnt[j]; }
            digit = lane*8 + j;
            newk  = k - (int)c;
        }
        digit = __shfl_sync(0xffffffffu, digit, src);
        k     = __shfl_sync(0xffffffffu, newk,  src);
        prefix |= ((unsigned)digit) << shift;
        __syncwarp();
    }
    return key2f(prefix);
}

// ---------------------------------------------------------------------------
// Per-row threshold + softmax stats. 8 warps/block, warp per row.
// Emits (thr, max, 1/den); P is never written back.
// ---------------------------------------------------------------------------
__global__ __launch_bounds__(256) void thresh_k(const int* __restrict__ amask)
{
    extern __shared__ float sm[];
    float* rows = sm;                           // 8*2560
    unsigned* hist = (unsigned*)(sm + 8*SK_);   // 8*256
    const int t = threadIdx.x, w = t>>5, lane = t&31;
    const int row_id = blockIdx.x*8 + w;
    const int bh = row_id >> 11;
    const int b = bh >> 4;
    const float* src = g_scores + (size_t)row_id*SK_;
    float* rw = rows + w*SK_;
    #pragma unroll
    for(int i=0;i<20;i++){
        int idx = (lane + i*32)*4;
        *(float4*)(rw+idx) = *(const float4*)(src+idx);
    }
    __syncwarp();
    float thr = warp_kth(rw, 256, hist + w*256, lane);   // keep iff x >= thr
    const int* am = amask + b*S_;
    float m = -1e30f;
    for(int i=lane;i<SK_;i+=32){
        float x = rw[i];
        if(x>=thr && (i<MEM_ || am[i-MEM_]!=0)) m = fmaxf(m,x);
    }
    #pragma unroll
    for(int off=16;off;off>>=1) m = fmaxf(m, __shfl_xor_sync(0xffffffffu,m,off));
    float den = 0.f;
    for(int i=lane;i<SK_;i+=32){
        float x = rw[i];
        den += (x>=thr && (i<MEM_ || am[i-MEM_]!=0)) ? __expf(x-m) : 0.f;
    }
    #pragma unroll
    for(int off=16;off;off>>=1) den += __shfl_xor_sync(0xffffffffu,den,off);
    if(lane==0) g_stats[row_id] = make_float4(thr, m, 1.f/den, 0.f);
}

// ---------------------------------------------------------------------------
// ctx = softmax(P) @ V, 3xTF32. Block: 256 q-rows x 64 dims, K chunks of 64.
// p = keep ? exp(x-m)/den : 0 applied during A staging. 8 warps (4m x 2n).
// ---------------------------------------------------------------------------
__global__ __launch_bounds__(256) void pv_k(const int* __restrict__ amask)
{
    extern __shared__ float sh[];
    float* Ps = sh;                       // [256][68]
    float* Vs = sh + 256*68;              // [64][72]
    float* thr_s = Vs + 64*72;            // 256
    float* max_s = thr_s + 256;
    float* inv_s = max_s + 256;
    const int z = blockIdx.y, m0 = blockIdx.x*256;
    const int b = z>>4, h = z&15;
    const int t = threadIdx.x, w=t>>5, lane=t&31, g=lane>>2, tig=lane&3;
    const int wm = w>>1, wn = w&1;
    const float* P = g_scores + ((size_t)(z*S_) + m0)*SK_;
    const float* V = g_v + (size_t)z*SK_*64;
    const int* am = amask + b*S_;
    const int pc = (t&15)*4;
    const int pr0 = t>>4;

    {
        float4 st = g_stats[(size_t)z*S_ + m0 + t];
        thr_s[t]=st.x; max_s[t]=st.y; inv_s[t]=st.z;
    }
    float acc[4][4][4];
    #pragma unroll
    for(int i=0;i<4;i++)
        #pragma unroll
        for(int j=0;j<4;j++)
            #pragma unroll
            for(int c=0;c<4;c++) acc[i][j][c]=0.f;
    __syncthreads();

    for(int kc=0;kc<40;kc++){
        const int k0 = kc*64;
        __syncthreads();                 // prior compute done before restage
        int mk[4];
        #pragma unroll
        for(int j=0;j<4;j++){ int kg = k0+pc+j; mk[j] = (kg<MEM_) ? 1 : am[kg-MEM_]; }
        #pragma unroll
        for(int i=0;i<4;i++){            // V chunk [k][n] stride 72
            int idx = t + i*256, r = idx>>4, c = (idx&15)*4;
            *(float4*)&Vs[r*72 + c] = *(const float4*)(V + (size_t)(k0+r)*64 + c);
        }
        #pragma unroll
        for(int i=0;i<16;i++){           // P chunk with exp transform
            int r = pr0 + i*16;
            float4 x = *(const float4*)(P + (size_t)r*SK_ + k0 + pc);
            float thr = thr_s[r], mm = max_s[r], iv = inv_s[r];
            float4 p;
            p.x = (mk[0] && x.x>=thr) ? __expf(x.x-mm)*iv : 0.f;
            p.y = (mk[1] && x.y>=thr) ? __expf(x.y-mm)*iv : 0.f;
            p.z = (mk[2] && x.z>=thr) ? __expf(x.z-mm)*iv : 0.f;
            p.w = (mk[3] && x.w>=thr) ? __expf(x.w-mm)*iv : 0.f;
            *(float4*)&Ps[r*68 + pc] = p;
        }
        __syncthreads();
        #pragma unroll
        for(int kk=0;kk<8;kk++){
            unsigned ah[4][4], al[4][4], bh[4][2], bl[4][2];
            #pragma unroll
            for(int mi=0;mi<4;mi++){
                const float* p = &Ps[(wm*64+mi*16+g)*68 + kk*8 + tig];
                tfsplit(p[0],      ah[mi][0], al[mi][0]);
                tfsplit(p[8*68],   ah[mi][1], al[mi][1]);
                tfsplit(p[4],      ah[mi][2], al[mi][2]);
                tfsplit(p[8*68+4], ah[mi][3], al[mi][3]);
            }
            #pragma unroll
            for(int nj=0;nj<4;nj++){
                const float* p = &Vs[(kk*8+tig)*72 + wn*32+nj*8+g];
                tfsplit(p[0],    bh[nj][0], bl[nj][0]);
                tfsplit(p[4*72], bh[nj][1], bl[nj][1]);
            }
            #pragma unroll
            for(int mi=0;mi<4;mi++)
                #pragma unroll
                for(int nj=0;nj<4;nj++)
                    mma8x3(acc[mi][nj], ah[mi], al[mi], bh[nj], bl[nj]);
        }
    }

    #pragma unroll
    for(int mi=0;mi<4;mi++){
        int r0 = m0 + wm*64+mi*16+g;
        #pragma unroll
        for(int nj=0;nj<4;nj++){
            int c0 = wn*32+nj*8+2*tig;
            float2 v0 = {acc[mi][nj][0], acc[mi][nj][1]};
            float2 v1 = {acc[mi][nj][2], acc[mi][nj][3]};
            *(float2*)(g_ctx + ((size_t)(b*S_ + r0))*1024 + h*64 + c0)   = v0;
            *(float2*)(g_ctx + ((size_t)(b*S_ + r0+8))*1024 + h*64 + c0) = v1;
        }
    }
}

// ---------------------------------------------------------------------------
extern "C" void kernel_launch(void* const* d_in, const int* in_sizes, int n_in,
                              void* d_out, int out_size)
{
    const float* hs     = (const float*)d_in[0];
    const int*   amask  = (const int*)  d_in[1];
    const float* past_k = (const float*)d_in[2];
    const float* past_v = (const float*)d_in[3];
    const float* Wq = (const float*)d_in[4];
    const float* bq = (const float*)d_in[5];
    const float* Wk = (const float*)d_in[6];
    const float* bk = (const float*)d_in[7];
    const float* Wv = (const float*)d_in[8];
    const float* bv = (const float*)d_in[9];
    const float* Wo = (const float*)d_in[10];
    const float* bo = (const float*)d_in[11];
    float* out = (float*)d_out;

    const int sc_smem = 2*128*68*4;                 // 69,632
    const int th_smem = (8*SK_ + 8*256)*4;          // 90,112
    const int pv_smem = (256*68 + 64*72 + 3*256)*4; // 91,136
    cudaFuncSetAttribute(scores_k, cudaFuncAttributeMaxDynamicSharedMemorySize, sc_smem);
    cudaFuncSetAttribute(thresh_k, cudaFuncAttributeMaxDynamicSharedMemorySize, th_smem);
    cudaFuncSetAttribute(pv_k,     cudaFuncAttributeMaxDynamicSharedMemorySize, pv_smem);

    copy_past_kernel<<<4096, 256>>>(past_k, past_v);

    dim3 gg(8, 32);
    gemm4k<<<gg, 256>>>(hs, Wq, bq, nullptr, 0);
    gemm4k<<<gg, 256>>>(hs, Wk, bk, nullptr, 1);
    gemm4k<<<gg, 256>>>(hs, Wv, bv, nullptr, 2);

    scores_k<<<dim3(20, 16, 32), 256, sc_smem>>>();
    thresh_k<<<NROW/8, 256, th_smem>>>(amask);
    pv_k<<<dim3(8, 32), 256, pv_smem>>>(amask);

    gemm4k<<<gg, 256>>>(nullptr, Wo, bo, out, 3);

    float* nk = out + (size_t)B_ * S_ * D_;
    float* nv = nk + (size_t)BH_ * MEM_ * HD_;
    copy_new_kernel<<<4096, 256>>>(nk, nv);
}

// round 5
// speedup vs baseline: 5.3287x; 1.0326x over previous
#include <cuda_runtime.h>

#define B_   2
#define S_   2048
#define D_   1024
#define H_   16
#define HD_  64
#define MEM_ 512
#define SK_  2560
#define BH_  32
#define NROW (BH_*S_)   // 65536
#define CAP_ 640        // per-warp candidate buffer for radix gather

// Scratch (static device allocs only)
__device__ float  g_q[BH_*S_*HD_];
__device__ float  g_k[BH_*SK_*HD_];
__device__ float  g_v[BH_*SK_*HD_];
__device__ float  g_ctx[B_*S_*D_];
__device__ float  g_scores[(size_t)NROW*SK_];   // 671 MB
__device__ float4 g_stats[NROW];                // thr, max, 1/den

__device__ __forceinline__ unsigned f2tf(float f){
    unsigned r; asm("cvt.rna.tf32.f32 %0, %1;" : "=r"(r) : "f"(f)); return r;
}
__device__ __forceinline__ void tfsplit(float x, unsigned& h, unsigned& l){
    h = f2tf(x);
    l = f2tf(x - __uint_as_float(h));
}
__device__ __forceinline__ void mma8(float* c, const unsigned* a, const unsigned* b){
    asm volatile("mma.sync.aligned.m16n8k8.row.col.f32.tf32.tf32.f32 "
      "{%0,%1,%2,%3}, {%4,%5,%6,%7}, {%8,%9}, {%0,%1,%2,%3};\n"
      : "+f"(c[0]), "+f"(c[1]), "+f"(c[2]), "+f"(c[3])
      : "r"(a[0]),"r"(a[1]),"r"(a[2]),"r"(a[3]), "r"(b[0]),"r"(b[1]));
}
__device__ __forceinline__ void mma8x3(float* c, const unsigned* ah, const unsigned* al,
                                       const unsigned* bh, const unsigned* bl){
    mma8(c, al, bh);
    mma8(c, ah, bl);
    mma8(c, ah, bh);
}

// ---------------------------------------------------------------------------
// Dense GEMM (3xTF32): C(4096x1024) = A(4096x1024)@W(1024x1024)+bias.
// ---------------------------------------------------------------------------
__global__ __launch_bounds__(256) void gemm4k(
    const float* __restrict__ A, const float* __restrict__ W,
    const float* __restrict__ bias, float* __restrict__ dst, int mode)
{
    __shared__ float As[2][128*20];
    __shared__ float Bs[2][16*136];
    const float* Ap = (mode==3) ? g_ctx : A;
    const int t = threadIdx.x;
    const int m0 = blockIdx.y*128, n0 = blockIdx.x*128;
    const int w = t>>5, lane = t&31, g = lane>>2, tig = lane&3;
    const int wm = w>>2, wn = w&3;

    const int am_r = t>>2;
    const int am_k = (t&3)*4;
    const int bm_k = t>>5;
    const int bm_n = (t&31)*4;

    const float* Arow0 = Ap + (size_t)(m0+am_r)*1024 + am_k;
    const float* Arow1 = Arow0 + (size_t)64*1024;
    const float* Wrow0 = W + (size_t)bm_k*1024 + n0 + bm_n;
    const float* Wrow1 = Wrow0 + (size_t)8*1024;

    float acc[4][4][4];
    #pragma unroll
    for(int i=0;i<4;i++)
        #pragma unroll
        for(int j=0;j<4;j++)
            #pragma unroll
            for(int c=0;c<4;c++) acc[i][j][c]=0.f;

    float4 la0,la1,lb0,lb1;
    auto ldg = [&](int kt){
        la0 = *(const float4*)(Arow0 + kt*16);
        la1 = *(const float4*)(Arow1 + kt*16);
        lb0 = *(const float4*)(Wrow0 + (size_t)kt*16*1024);
        lb1 = *(const float4*)(Wrow1 + (size_t)kt*16*1024);
    };
    auto sts = [&](int buf){
        *(float4*)&As[buf][am_r*20 + am_k]      = la0;
        *(float4*)&As[buf][(am_r+64)*20 + am_k] = la1;
        *(float4*)&Bs[buf][bm_k*136 + bm_n]     = lb0;
        *(float4*)&Bs[buf][(bm_k+8)*136 + bm_n] = lb1;
    };
    auto compute = [&](int buf){
        #pragma unroll
        for(int kk=0;kk<2;kk++){
            unsigned ah[4][4], al[4][4], bh[4][2], bl[4][2];
            #pragma unroll
            for(int mi=0;mi<4;mi++){
                const float* p = &As[buf][(wm*64+mi*16+g)*20 + kk*8 + tig];
                tfsplit(p[0],      ah[mi][0], al[mi][0]);
                tfsplit(p[8*20],   ah[mi][1], al[mi][1]);
                tfsplit(p[4],      ah[mi][2], al[mi][2]);
                tfsplit(p[8*20+4], ah[mi][3], al[mi][3]);
            }
            #pragma unroll
            for(int nj=0;nj<4;nj++){
                const float* p = &Bs[buf][(kk*8+tig)*136 + wn*32+nj*8+g];
                tfsplit(p[0],     bh[nj][0], bl[nj][0]);
                tfsplit(p[4*136], bh[nj][1], bl[nj][1]);
            }
            #pragma unroll
            for(int mi=0;mi<4;mi++)
                #pragma unroll
                for(int nj=0;nj<4;nj++)
                    mma8x3(acc[mi][nj], ah[mi], al[mi], bh[nj], bl[nj]);
        }
    };

    ldg(0); sts(0); __syncthreads();
    for(int kt=0;kt<64;kt++){
        if(kt<63) ldg(kt+1);
        compute(kt&1);
        if(kt<63){ sts((kt+1)&1); __syncthreads(); }
    }

    const int b = m0>>11;
    #pragma unroll
    for(int nj=0;nj<4;nj++){
        int c0 = n0 + wn*32 + nj*8 + 2*tig;
        float bv0 = bias[c0], bv1 = bias[c0+1];
        int h = c0>>6, hd = c0&63;
        #pragma unroll
        for(int mi=0;mi<4;mi++){
            int r0 = m0 + wm*64 + mi*16 + g;
            int s0 = r0 & 2047;
            float2 v0 = {acc[mi][nj][0]+bv0, acc[mi][nj][1]+bv1};
            float2 v1 = {acc[mi][nj][2]+bv0, acc[mi][nj][3]+bv1};
            if(mode==3){
                *(float2*)(dst + (size_t)r0*1024 + c0)     = v0;
                *(float2*)(dst + (size_t)(r0+8)*1024 + c0) = v1;
            } else {
                float* base = (mode==0)? g_q : (mode==1? g_k : g_v);
                size_t roff = (mode==0)? ((size_t)(b*16+h)*S_)
                                        : ((size_t)(b*16+h)*SK_ + MEM_);
                *(float2*)(base + (roff + s0)*64 + hd)     = v0;
                *(float2*)(base + (roff + s0 + 8)*64 + hd) = v1;
            }
        }
    }
}

__global__ void copy_past_kernel(const float* __restrict__ pk,
                                 const float* __restrict__ pv)
{
    int i = blockIdx.x * blockDim.x + threadIdx.x;
    if (i < BH_ * MEM_ * HD_ / 4) {
        int e = i * 4;
        int bh = e >> 15, rem = e & 32767;
        *(float4*)(g_k + (size_t)bh*(SK_*HD_) + rem) = *(const float4*)(pk + e);
        *(float4*)(g_v + (size_t)bh*(SK_*HD_) + rem) = *(const float4*)(pv + e);
    }
}
__global__ void copy_new_kernel(float* __restrict__ nk, float* __restrict__ nv)
{
    int i = blockIdx.x * blockDim.x + threadIdx.x;
    if (i < BH_ * MEM_ * HD_ / 4) {
        int e = i * 4;
        int bh = e >> 15, rem = e & 32767;
        size_t src = (size_t)bh*(SK_*HD_) + S_*HD_ + rem;
        *(float4*)(nk + e) = *(const float4*)(g_k + src);
        *(float4*)(nv + e) = *(const float4*)(g_v + src);
    }
}

// ---------------------------------------------------------------------------
// scores = (Q K^T) * 0.125 -> g_scores. 3xTF32, K=64. Block 128x128 per bh.
// ---------------------------------------------------------------------------
__global__ __launch_bounds__(256) void scores_k()
{
    extern __shared__ float sh[];
    float* Qs = sh;               // [128][68]
    float* Ks = sh + 128*68;      // [128][68]
    const int z = blockIdx.z;
    const int m0 = blockIdx.y*128, n0 = blockIdx.x*128;
    const int t = threadIdx.x, w = t>>5, lane=t&31, g=lane>>2, tig=lane&3;
    const int wm = w>>2, wn = w&3;
    const float* Q = g_q + ((size_t)z*S_ + m0)*64;
    const float* K = g_k + ((size_t)z*SK_ + n0)*64;

    #pragma unroll
    for(int i=0;i<8;i++){
        int idx = t + i*256, r = idx>>4, c = (idx&15)*4;
        *(float4*)&Qs[r*68+c] = *(const float4*)(Q + (size_t)r*64 + c);
        *(float4*)&Ks[r*68+c] = *(const float4*)(K + (size_t)r*64 + c);
    }
    __syncthreads();

    float acc[4][4][4] = {};
    #pragma unroll
    for(int kk=0;kk<8;kk++){
        unsigned ah[4][4], al[4][4], bh[4][2], bl[4][2];
        #pragma unroll
        for(int mi=0;mi<4;mi++){
            const float* p = &Qs[(wm*64+mi*16+g)*68 + kk*8 + tig];
            tfsplit(p[0],      ah[mi][0], al[mi][0]);
            tfsplit(p[8*68],   ah[mi][1], al[mi][1]);
            tfsplit(p[4],      ah[mi][2], al[mi][2]);
            tfsplit(p[8*68+4], ah[mi][3], al[mi][3]);
        }
        #pragma unroll
        for(int nj=0;nj<4;nj++){
            const float* p = &Ks[(wn*32+nj*8+g)*68 + kk*8 + tig];
            tfsplit(p[0], bh[nj][0], bl[nj][0]);
            tfsplit(p[4], bh[nj][1], bl[nj][1]);
        }
        #pragma unroll
        for(int mi=0;mi<4;mi++)
            #pragma unroll
            for(int nj=0;nj<4;nj++)
                mma8x3(acc[mi][nj], ah[mi], al[mi], bh[nj], bl[nj]);
    }

    float* out = g_scores + ((size_t)(z*S_ + m0))*SK_ + n0;
    #pragma unroll
    for(int mi=0;mi<4;mi++){
        int r0 = wm*64+mi*16+g;
        #pragma unroll
        for(int nj=0;nj<4;nj++){
            int c0 = wn*32+nj*8+2*tig;
            float2 v0 = {acc[mi][nj][0]*0.125f, acc[mi][nj][1]*0.125f};
            float2 v1 = {acc[mi][nj][2]*0.125f, acc[mi][nj][3]*0.125f};
            *(float2*)(out + (size_t)r0*SK_ + c0)     = v0;
            *(float2*)(out + (size_t)(r0+8)*SK_ + c0) = v1;
        }
    }
}

// ---------------------------------------------------------------------------
// Radix helpers
// ---------------------------------------------------------------------------
__device__ __forceinline__ unsigned f2key(float f) {
    unsigned u = __float_as_uint(f);
    return (u & 0x80000000u) ? ~u : (u | 0x80000000u);
}
__device__ __forceinline__ float key2f(unsigned k) {
    unsigned u = (k & 0x80000000u) ? (k ^ 0x80000000u) : ~k;
    return __uint_as_float(u);
}
// Pick digit containing rank k from a 256-bin hist; updates k to rank-in-bin.
__device__ __forceinline__ int resolve256(const unsigned* hist, int lane, int& k){
    unsigned cnt[8], local = 0;
    #pragma unroll
    for (int j = 0; j < 8; j++) { cnt[j] = hist[lane*8+j]; local += cnt[j]; }
    unsigned x = local;
    #pragma unroll
    for (int off = 1; off < 32; off <<= 1) {
        unsigned y = __shfl_up_sync(0xffffffffu, x, off);
        if (lane >= off) x += y;
    }
    unsigned incl = x, excl = x - local;
    bool flag = ((unsigned)k >= excl) && ((unsigned)k < incl);
    unsigned bal = __ballot_sync(0xffffffffu, flag);
    int src = __ffs(bal) - 1;
    int digit = 0, newk = 0;
    if (lane == src) {
        unsigned c = excl; int j = 0;
        for (; j < 8; j++) { if (c + cnt[j] > (unsigned)k) break; c += cnt[j]; }
        digit = lane*8 + j;
        newk  = k - (int)c;
    }
    digit = __shfl_sync(0xffffffffu, digit, src);
    k     = __shfl_sync(0xffffffffu, newk,  src);
    return digit;
}

// ---------------------------------------------------------------------------
// Per-row threshold + softmax stats. Warp per row. Candidate-gather radix:
// pass 1 full-row hist, gather matching-prefix keys into compact buffer,
// passes 2-4 scan only candidates (fallback to full scans if > CAP_).
// Masked max fused into the gmem->smem copy. Emits (thr, max, 1/den).
// ---------------------------------------------------------------------------
__global__ __launch_bounds__(256) void thresh_k(const int* __restrict__ amask)
{
    extern __shared__ float sm[];
    float*    rows = sm;                              // 8*2560
    unsigned* cand = (unsigned*)(sm + 8*SK_);         // 8*CAP_
    unsigned* hist = cand + 8*CAP_;                   // 8*264 (256 bins + counter)
    const int t = threadIdx.x, w = t>>5, lane = t&31;
    const int row_id = blockIdx.x*8 + w;
    const int bh = row_id >> 11;
    const int b = bh >> 4;
    const float* src = g_scores + (size_t)row_id*SK_;
    const int* am = amask + b*S_;
    float*    rw = rows + w*SK_;
    unsigned* cw = cand + w*CAP_;
    unsigned* hw = hist + w*264;

    // copy + masked max
    float m = -1e30f;
    #pragma unroll
    for(int i=0;i<20;i++){
        int idx = (lane + i*32)*4;
        float4 v = *(const float4*)(src+idx);
        *(float4*)(rw+idx) = v;
        #pragma unroll
        for(int j=0;j<4;j++){
            int kg = idx + j;
            float x = (&v.x)[j];
            bool ok = (kg < MEM_) || (am[kg-MEM_] != 0);
            if (ok) m = fmaxf(m, x);
        }
    }
    #pragma unroll
    for(int off=16;off;off>>=1) m = fmaxf(m, __shfl_xor_sync(0xffffffffu,m,off));

    // radix pass 1 (top 8 bits) over full row
    int k = 256;
    for(int i=lane;i<256;i+=32) hw[i]=0;
    __syncwarp();
    for(int i=lane;i<SK_;i+=32) atomicAdd(&hw[f2key(rw[i])>>24], 1u);
    __syncwarp();
    int d0 = resolve256(hw, lane, k);
    unsigned prefix = (unsigned)d0 << 24;

    // gather candidates matching top-8 prefix
    if(lane==0) hw[256]=0;
    __syncwarp();
    for(int i=lane;i<SK_;i+=32){
        unsigned key = f2key(rw[i]);
        if ((key>>24) == (unsigned)d0){
            unsigned p = atomicAdd(&hw[256], 1u);
            if (p < CAP_) cw[p] = key;
        }
    }
    __syncwarp();
    int c = hw[256];

    if (c <= CAP_) {
        for(int shift=16; shift>=0; shift-=8){
            for(int i=lane;i<256;i+=32) hw[i]=0;
            __syncwarp();
            unsigned hm = 0xFFFFFFFFu << (shift+8);
            for(int i=lane;i<c;i+=32){
                unsigned key = cw[i];
                if ((key & hm) == (prefix & hm))
                    atomicAdd(&hw[(key>>shift)&255], 1u);
            }
            __syncwarp();
            int d = resolve256(hw, lane, k);
            prefix |= (unsigned)d << shift;
            __syncwarp();
        }
    } else {
        // fallback: full-row predicate scans (degenerate distributions)
        for(int shift=16; shift>=0; shift-=8){
            for(int i=lane;i<256;i+=32) hw[i]=0;
            __syncwarp();
            unsigned hm = 0xFFFFFFFFu << (shift+8);
            for(int i=lane;i<SK_;i+=32){
                unsigned key = f2key(rw[i]);
                if ((key & hm) == prefix)
                    atomicAdd(&hw[(key>>shift)&255], 1u);
            }
            __syncwarp();
            int d = resolve256(hw, lane, k);
            prefix |= (unsigned)d << shift;
            __syncwarp();
        }
    }
    float thr = key2f(prefix);   // keep iff x >= thr

    // denominator over keep-set ∩ mask
    float den = 0.f;
    for(int i=lane;i<SK_;i+=32){
        float x = rw[i];
        bool ok = (x >= thr) && (i < MEM_ || am[i-MEM_] != 0);
        den += ok ? __expf(x - m) : 0.f;
    }
    #pragma unroll
    for(int off=16;off;off>>=1) den += __shfl_xor_sync(0xffffffffu,den,off);
    if(lane==0) g_stats[row_id] = make_float4(thr, m, 1.f/den, 0.f);
}

// ---------------------------------------------------------------------------
// ctx = softmax(P) @ V, single-pass tf32 (analog-noise stage; error budget ok).
// Block: 256 q-rows x 64 dims, K chunks of 64. exp applied during A staging.
// ---------------------------------------------------------------------------
__global__ __launch_bounds__(256) void pv_k(const int* __restrict__ amask)
{
    extern __shared__ unsigned shu[];
    unsigned* Ps = shu;                       // [256][68]
    unsigned* Vs = shu + 256*68;              // [64][72]
    float* thr_s = (float*)(Vs + 64*72);      // 256
    float* max_s = thr_s + 256;
    float* inv_s = max_s + 256;
    const int z = blockIdx.y, m0 = blockIdx.x*256;
    const int b = z>>4, h = z&15;
    const int t = threadIdx.x, w=t>>5, lane=t&31, g=lane>>2, tig=lane&3;
    const int wm = w>>1, wn = w&1;
    const float* P = g_scores + ((size_t)(z*S_) + m0)*SK_;
    const float* V = g_v + (size_t)z*SK_*64;
    const int* am = amask + b*S_;
    const int pc = (t&15)*4;
    const int pr0 = t>>4;

    {
        float4 st = g_stats[(size_t)z*S_ + m0 + t];
        thr_s[t]=st.x; max_s[t]=st.y; inv_s[t]=st.z;
    }
    float acc[4][4][4];
    #pragma unroll
    for(int i=0;i<4;i++)
        #pragma unroll
        for(int j=0;j<4;j++)
            #pragma unroll
            for(int c=0;c<4;c++) acc[i][j][c]=0.f;
    __syncthreads();

    for(int kc=0;kc<40;kc++){
        const int k0 = kc*64;
        __syncthreads();
        int mk[4];
        #pragma unroll
        for(int j=0;j<4;j++){ int kg = k0+pc+j; mk[j] = (kg<MEM_) ? 1 : am[kg-MEM_]; }
        #pragma unroll
        for(int i=0;i<4;i++){            // V chunk [k][n] stride 72
            int idx = t + i*256, r = idx>>4, c = (idx&15)*4;
            float4 v = *(const float4*)(V + (size_t)(k0+r)*64 + c);
            uint4 u = {f2tf(v.x),f2tf(v.y),f2tf(v.z),f2tf(v.w)};
            *(uint4*)&Vs[r*72 + c] = u;
        }
        #pragma unroll
        for(int i=0;i<16;i++){           // P chunk with exp transform
            int r = pr0 + i*16;
            float4 x = *(const float4*)(P + (size_t)r*SK_ + k0 + pc);
            float thr = thr_s[r], mm = max_s[r], iv = inv_s[r];
            float p0 = (mk[0] && x.x>=thr) ? __expf(x.x-mm)*iv : 0.f;
            float p1 = (mk[1] && x.y>=thr) ? __expf(x.y-mm)*iv : 0.f;
            float p2 = (mk[2] && x.z>=thr) ? __expf(x.z-mm)*iv : 0.f;
            float p3 = (mk[3] && x.w>=thr) ? __expf(x.w-mm)*iv : 0.f;
            uint4 u = {f2tf(p0),f2tf(p1),f2tf(p2),f2tf(p3)};
            *(uint4*)&Ps[r*68 + pc] = u;
        }
        __syncthreads();
        #pragma unroll
        for(int kk=0;kk<8;kk++){
            unsigned af[4][4], bf[4][2];
            #pragma unroll
            for(int mi=0;mi<4;mi++){
                const unsigned* p = &Ps[(wm*64+mi*16+g)*68 + kk*8 + tig];
                af[mi][0]=p[0]; af[mi][1]=p[8*68]; af[mi][2]=p[4]; af[mi][3]=p[8*68+4];
            }
            #pragma unroll
            for(int nj=0;nj<4;nj++){
                const unsigned* p = &Vs[(kk*8+tig)*72 + wn*32+nj*8+g];
                bf[nj][0]=p[0]; bf[nj][1]=p[4*72];
            }
            #pragma unroll
            for(int mi=0;mi<4;mi++)
                #pragma unroll
                for(int nj=0;nj<4;nj++) mma8(acc[mi][nj], af[mi], bf[nj]);
        }
    }

    #pragma unroll
    for(int mi=0;mi<4;mi++){
        int r0 = m0 + wm*64+mi*16+g;
        #pragma unroll
        for(int nj=0;nj<4;nj++){
            int c0 = wn*32+nj*8+2*tig;
            float2 v0 = {acc[mi][nj][0], acc[mi][nj][1]};
            float2 v1 = {acc[mi][nj][2], acc[mi][nj][3]};
            *(float2*)(g_ctx + ((size_t)(b*S_ + r0))*1024 + h*64 + c0)   = v0;
            *(float2*)(g_ctx + ((size_t)(b*S_ + r0+8))*1024 + h*64 + c0) = v1;
        }
    }
}

// ---------------------------------------------------------------------------
extern "C" void kernel_launch(void* const* d_in, const int* in_sizes, int n_in,
                              void* d_out, int out_size)
{
    const float* hs     = (const float*)d_in[0];
    const int*   amask  = (const int*)  d_in[1];
    const float* past_k = (const float*)d_in[2];
    const float* past_v = (const float*)d_in[3];
    const float* Wq = (const float*)d_in[4];
    const float* bq = (const float*)d_in[5];
    const float* Wk = (const float*)d_in[6];
    const float* bk = (const float*)d_in[7];
    const float* Wv = (const float*)d_in[8];
    const float* bv = (const float*)d_in[9];
    const float* Wo = (const float*)d_in[10];
    const float* bo = (const float*)d_in[11];
    float* out = (float*)d_out;

    const int sc_smem = 2*128*68*4;                        // 69,632
    const int th_smem = (8*SK_)*4 + 8*CAP_*4 + 8*264*4;    // 110,848
    const int pv_smem = (256*68 + 64*72 + 3*256)*4;        // 91,136
    cudaFuncSetAttribute(scores_k, cudaFuncAttributeMaxDynamicSharedMemorySize, sc_smem);
    cudaFuncSetAttribute(thresh_k, cudaFuncAttributeMaxDynamicSharedMemorySize, th_smem);
    cudaFuncSetAttribute(pv_k,     cudaFuncAttributeMaxDynamicSharedMemorySize, pv_smem);

    copy_past_kernel<<<1024, 256>>>(past_k, past_v);

    dim3 gg(8, 32);
    gemm4k<<<gg, 256>>>(hs, Wq, bq, nullptr, 0);
    gemm4k<<<gg, 256>>>(hs, Wk, bk, nullptr, 1);
    gemm4k<<<gg, 256>>>(hs, Wv, bv, nullptr, 2);

    scores_k<<<dim3(20, 16, 32), 256, sc_smem>>>();
    thresh_k<<<NROW/8, 256, th_smem>>>(amask);
    pv_k<<<dim3(8, 32), 256, pv_smem>>>(amask);

    gemm4k<<<gg, 256>>>(nullptr, Wo, bo, out, 3);

    float* nk = out + (size_t)B_ * S_ * D_;
    float* nv = nk + (size_t)BH_ * MEM_ * HD_;
    copy_new_kernel<<<1024, 256>>>(nk, nv);
}